// round 12
// baseline (speedup 1.0000x reference)
#include <cuda_runtime.h>
#include <cuda_fp16.h>

// Morphological dilation2d, K=7, PAD=3 (zero padding = nn.Unfold), then ReLU.
// out[b,c,h,w] = max(0, max_{i,j}( xp[b,c,h+i,w+j] + weight[c,i,j] ))
// Packed fp16x2 (HADD2 + HMNMX2); ReLU folded into acc init (=0).
// R9 structure (PRMT shift in registers, single slab) + paired weight table
// (one broadcast LDS.64 per tap fetches both weight rows) + 8 CTAs/SM.
//
// x:      (16, 96, 128, 128) fp32 -> d_in[0]
// weight: (96, 7, 7)         fp32 -> d_in[1]
// out:    fp32

#define HH    128
#define WW    128
#define CC    96
#define BB    16
#define RPC   32            // output rows per CTA
#define SR    38            // smem rows = RPC + 6
#define SROWH 136           // smem row stride in HALVES (272B)
#define NT    256

__device__ __forceinline__ __half2 u2h(unsigned u) { return *reinterpret_cast<__half2*>(&u); }

__global__ __launch_bounds__(NT, 8)
void morph7x7_h2_kernel(const float* __restrict__ x,
                        const float* __restrict__ wt,
                        float* __restrict__ out) {
    __shared__ __half xs[SR * SROWH];
    __shared__ uint2  wp[56];               // (w2[s][j], w2[s-1][j]) broadcast pairs

    const int bid   = blockIdx.x;
    const int rtile = bid & 3;
    const int plane = bid >> 2;             // b*CC + c
    const int c     = plane % CC;
    const int R0    = rtile * RPC;

    const float* gx = x   + (size_t)plane * (HH * WW);
    float*       go = out + (size_t)plane * (HH * WW);
    const int tid = threadIdx.x;

    // ---- zero slab (borders must be literal zeros) ----
    const uint4 z4 = {0u, 0u, 0u, 0u};
    #pragma unroll
    for (int i = tid; i < (SR * SROWH) / 8; i += NT)
        reinterpret_cast<uint4*>(xs)[i] = z4;

    // ---- paired weight table: wp[s*7+j] = (row s (s<7), row s-1 (s>0)) ----
    if (tid < 56) {
        const int s = tid / 7, j = tid % 7;
        unsigned w0 = 0u, w1 = 0u;
        if (s < 7) {
            __half2 h2 = __half2half2(__float2half_rn(wt[c * 49 + s * 7 + j]));
            w0 = *reinterpret_cast<unsigned*>(&h2);
        }
        if (s > 0) {
            __half2 h2 = __half2half2(__float2half_rn(wt[c * 49 + (s - 1) * 7 + j]));
            w1 = *reinterpret_cast<unsigned*>(&h2);
        }
        wp[tid] = make_uint2(w0, w1);
    }
    __syncthreads();

    // ---- load interior rows [g0,g1), fp32 -> fp16, data at half-col 4 ----
    const int g0 = (R0 - 3 > 0) ? R0 - 3 : 0;
    const int g1 = (R0 + 35 < HH) ? R0 + 35 : HH;
    const int n4 = (g1 - g0) * 32;          // float4 count
    #pragma unroll
    for (int idx = tid; idx < n4; idx += NT) {
        const int rr = idx >> 5;
        const int c4 = idx & 31;
        const int g  = g0 + rr;
        float4 v = reinterpret_cast<const float4*>(gx + g * WW)[c4];
        __half2 p0 = __floats2half2_rn(v.x, v.y);
        __half2 p1 = __floats2half2_rn(v.z, v.w);
        __half2* dst = reinterpret_cast<__half2*>(&xs[(g + 3 - R0) * SROWH + 4 + c4 * 4]);
        dst[0] = p0;
        dst[1] = p1;
    }
    __syncthreads();

    // ---- compute: thread = 8 cols x 2 rows ----
    const int tx    = tid & 15;
    const int ty    = tid >> 4;
    const int cbase = tx * 8;               // output col base; LDS.128-aligned reads
    const int r0    = ty * 2;

    // S[0..3]=0 pad; taps for output col w are S[w+1 .. w+7].
    const uint4* rb = reinterpret_cast<const uint4*>(&xs[r0 * SROWH + cbase]);

    __half2 acc0[4], acc1[4];
    const __half2 h2z = __float2half2_rn(0.0f);
    #pragma unroll
    for (int p = 0; p < 4; ++p) { acc0[p] = h2z; acc1[p] = h2z; }   // folds ReLU

    #pragma unroll
    for (int s = 0; s < 8; ++s) {
        const uint4 A = rb[s * 17];
        const uint4 B = rb[s * 17 + 1];
        const unsigned h[8] = {A.x, A.y, A.z, A.w, B.x, B.y, B.z, B.w};
        unsigned sft[7];
        #pragma unroll
        for (int m = 0; m < 7; ++m) sft[m] = __byte_perm(h[m], h[m + 1], 0x5432);

        // tap j, output pair p: j even -> sft[j/2+p], j odd -> h[(j+1)/2+p]
        // acc0 uses weight row s (s<7); acc1 uses weight row s-1 (s>0).
        #pragma unroll
        for (int j = 0; j < 7; ++j) {
            const uint2 w = wp[s * 7 + j];       // one broadcast LDS.64, both rows
            #pragma unroll
            for (int p = 0; p < 4; ++p) {
                const __half2 tap = (j & 1) ? u2h(h[((j + 1) >> 1) + p])
                                            : u2h(sft[(j >> 1) + p]);
                if (s < 7) acc0[p] = __hmax2(acc0[p], __hadd2(tap, u2h(w.x)));
                if (s > 0) acc1[p] = __hmax2(acc1[p], __hadd2(tap, u2h(w.y)));
            }
        }
    }

    // ---- convert fp16 -> fp32, store 2x STG.128 per row ----
    {
        float2 f0 = __half22float2(acc0[0]);
        float2 f1 = __half22float2(acc0[1]);
        float2 f2 = __half22float2(acc0[2]);
        float2 f3 = __half22float2(acc0[3]);
        float4* op = reinterpret_cast<float4*>(&go[(R0 + r0) * WW + cbase]);
        op[0] = make_float4(f0.x, f0.y, f1.x, f1.y);
        op[1] = make_float4(f2.x, f2.y, f3.x, f3.y);
    }
    {
        float2 f0 = __half22float2(acc1[0]);
        float2 f1 = __half22float2(acc1[1]);
        float2 f2 = __half22float2(acc1[2]);
        float2 f3 = __half22float2(acc1[3]);
        float4* op = reinterpret_cast<float4*>(&go[(R0 + r0 + 1) * WW + cbase]);
        op[0] = make_float4(f0.x, f0.y, f1.x, f1.y);
        op[1] = make_float4(f2.x, f2.y, f3.x, f3.y);
    }
}

extern "C" void kernel_launch(void* const* d_in, const int* in_sizes, int n_in,
                              void* d_out, int out_size) {
    const float* x  = (const float*)d_in[0];
    const float* wt = (const float*)d_in[1];
    float* out = (float*)d_out;
    morph7x7_h2_kernel<<<BB * CC * 4, NT>>>(x, wt, out);
}

// round 13
// speedup vs baseline: 1.0347x; 1.0347x over previous
#include <cuda_runtime.h>
#include <cuda_fp16.h>

// Morphological dilation2d, K=7, PAD=3 (zero padding = nn.Unfold), then ReLU.
// out[b,c,h,w] = max(0, max_{i,j}( xp[b,c,h+i,w+j] + weight[c,i,j] ))
// Packed fp16x2 (HADD2 + HMNMX2); ReLU folded into acc init (=0).
//
// Persistent kernel: grid = 888 (exactly 6 CTAs/SM x 148 SMs = one wave);
// each CTA loops over tiles stride-888, eliminating wave-transition gaps.
// Paired weight table: one broadcast LDS.64 per tap fetches both kernel rows.
//
// x:      (16, 96, 128, 128) fp32 -> d_in[0]
// weight: (96, 7, 7)         fp32 -> d_in[1]
// out:    fp32

#define HH    128
#define WW    128
#define CC    96
#define BB    16
#define RPC   32            // output rows per tile
#define SR    38            // smem rows = RPC + 6
#define SROWH 136           // smem row stride in HALVES (272B)
#define NT    256
#define NTILES (BB * CC * 4)
#define CONC  888           // 148 SMs * 6 CTAs

__device__ __forceinline__ __half2 u2h(unsigned u) { return *reinterpret_cast<__half2*>(&u); }

__global__ __launch_bounds__(NT, 6)
void morph7x7_h2_kernel(const float* __restrict__ x,
                        const float* __restrict__ wt,
                        float* __restrict__ out) {
    __shared__ __half xs[SR * SROWH];
    __shared__ uint2  wp[56];               // (w2[s][j], w2[s-1][j]) broadcast pairs

    const int tid = threadIdx.x;

    // ---- one-time full zero: establishes side halo cols + row stripes ----
    const uint4 z4 = {0u, 0u, 0u, 0u};
    #pragma unroll
    for (int i = tid; i < (SR * SROWH) / 8; i += NT)
        reinterpret_cast<uint4*>(xs)[i] = z4;
    // (no barrier needed yet; first loop iteration has one before fill)

    const int tx    = tid & 15;
    const int ty    = tid >> 4;
    const int cbase = tx * 8;               // output col base; LDS.128-aligned reads
    const int r0    = ty * 2;
    const uint4* rb = reinterpret_cast<const uint4*>(&xs[r0 * SROWH + cbase]);
    const __half2 h2z = __float2half2_rn(0.0f);

    for (int t = blockIdx.x; t < NTILES; t += CONC) {
        const int rtile = t & 3;
        const int plane = t >> 2;           // b*CC + c
        const int c     = plane % CC;
        const int R0    = rtile * RPC;
        const float* gx = x   + (size_t)plane * (HH * WW);
        float*       go = out + (size_t)plane * (HH * WW);

        // ---- re-zero top/bottom halo row stripes (rows 0-2 and 35-37) ----
        // Side halo cols were zeroed once and are never overwritten.
        if (tid < 102) {                    // 6 rows * 17 uint4
            const int rr  = tid / 17;       // 0..5
            const int cc4 = tid % 17;
            const int row = (rr < 3) ? rr : (35 + rr - 3);
            reinterpret_cast<uint4*>(&xs[row * SROWH])[cc4] = z4;
        }
        // ---- paired weight table: wp[s*7+j] = (row s (s<7), row s-1 (s>0)) ----
        if (tid >= 128 && tid < 184) {
            const int k = tid - 128;
            const int s = k / 7, j = k % 7;
            unsigned w0 = 0u, w1 = 0u;
            if (s < 7) {
                __half2 h2 = __half2half2(__float2half_rn(wt[c * 49 + s * 7 + j]));
                w0 = *reinterpret_cast<unsigned*>(&h2);
            }
            if (s > 0) {
                __half2 h2 = __half2half2(__float2half_rn(wt[c * 49 + (s - 1) * 7 + j]));
                w1 = *reinterpret_cast<unsigned*>(&h2);
            }
            wp[k] = make_uint2(w0, w1);
        }
        __syncthreads();

        // ---- fill interior rows [g0,g1), fp32 -> fp16, data at half-col 4 ----
        const int g0 = (R0 - 3 > 0) ? R0 - 3 : 0;
        const int g1 = (R0 + 35 < HH) ? R0 + 35 : HH;
        const int n4 = (g1 - g0) * 32;      // float4 count
        #pragma unroll 4
        for (int idx = tid; idx < n4; idx += NT) {
            const int rr = idx >> 5;
            const int c4 = idx & 31;
            const int g  = g0 + rr;
            float4 v = reinterpret_cast<const float4*>(gx + g * WW)[c4];
            __half2 p0 = __floats2half2_rn(v.x, v.y);
            __half2 p1 = __floats2half2_rn(v.z, v.w);
            __half2* dst = reinterpret_cast<__half2*>(&xs[(g + 3 - R0) * SROWH + 4 + c4 * 4]);
            dst[0] = p0;
            dst[1] = p1;
        }
        __syncthreads();

        // ---- compute: thread = 8 cols x 2 rows ----
        __half2 acc0[4], acc1[4];
        #pragma unroll
        for (int p = 0; p < 4; ++p) { acc0[p] = h2z; acc1[p] = h2z; }  // folds ReLU

        #pragma unroll
        for (int s = 0; s < 8; ++s) {
            const uint4 A = rb[s * 17];
            const uint4 B = rb[s * 17 + 1];
            const unsigned h[8] = {A.x, A.y, A.z, A.w, B.x, B.y, B.z, B.w};
            unsigned sft[7];
            #pragma unroll
            for (int m = 0; m < 7; ++m) sft[m] = __byte_perm(h[m], h[m + 1], 0x5432);

            // tap j, output pair p: j even -> sft[j/2+p], j odd -> h[(j+1)/2+p]
            // acc0 uses weight row s (s<7); acc1 uses weight row s-1 (s>0).
            #pragma unroll
            for (int j = 0; j < 7; ++j) {
                const uint2 w = wp[s * 7 + j];      // one broadcast LDS.64, both rows
                #pragma unroll
                for (int p = 0; p < 4; ++p) {
                    const __half2 tap = (j & 1) ? u2h(h[((j + 1) >> 1) + p])
                                                : u2h(sft[(j >> 1) + p]);
                    if (s < 7) acc0[p] = __hmax2(acc0[p], __hadd2(tap, u2h(w.x)));
                    if (s > 0) acc1[p] = __hmax2(acc1[p], __hadd2(tap, u2h(w.y)));
                }
            }
        }

        // ---- convert fp16 -> fp32, store 2x STG.128 per row ----
        {
            float2 f0 = __half22float2(acc0[0]);
            float2 f1 = __half22float2(acc0[1]);
            float2 f2 = __half22float2(acc0[2]);
            float2 f3 = __half22float2(acc0[3]);
            float4* op = reinterpret_cast<float4*>(&go[(R0 + r0) * WW + cbase]);
            op[0] = make_float4(f0.x, f0.y, f1.x, f1.y);
            op[1] = make_float4(f2.x, f2.y, f3.x, f3.y);
        }
        {
            float2 f0 = __half22float2(acc1[0]);
            float2 f1 = __half22float2(acc1[1]);
            float2 f2 = __half22float2(acc1[2]);
            float2 f3 = __half22float2(acc1[3]);
            float4* op = reinterpret_cast<float4*>(&go[(R0 + r0 + 1) * WW + cbase]);
            op[0] = make_float4(f0.x, f0.y, f1.x, f1.y);
            op[1] = make_float4(f2.x, f2.y, f3.x, f3.y);
        }

        __syncthreads();   // xs/wp reused next iteration
    }
}

extern "C" void kernel_launch(void* const* d_in, const int* in_sizes, int n_in,
                              void* d_out, int out_size) {
    const float* x  = (const float*)d_in[0];
    const float* wt = (const float*)d_in[1];
    float* out = (float*)d_out;
    morph7x7_h2_kernel<<<CONC, NT>>>(x, wt, out);
}

// round 14
// speedup vs baseline: 1.1161x; 1.0786x over previous
#include <cuda_runtime.h>
#include <cuda_fp16.h>

// Morphological dilation2d, K=7, PAD=3 (zero padding = nn.Unfold), then ReLU.
// out[b,c,h,w] = max(0, max_{i,j}( xp[b,c,h+i,w+j] + weight[c,i,j] ))
// Packed fp16x2 (HADD2 + HMNMX2); ReLU folded into acc init (=0).
//
// R9 geometry (grid 6144, 6 CTAs/SM, 6.92 waves) + quad-paired weight table:
// wq[s*4+q] = (w2[s][2q], w2[s-1][2q], w2[s][2q+1], w2[s-1][2q+1]) so one
// broadcast LDS.128 serves two taps x two kernel rows (32 loads vs 98).
//
// x:      (16, 96, 128, 128) fp32 -> d_in[0]
// weight: (96, 7, 7)         fp32 -> d_in[1]
// out:    fp32

#define HH    128
#define WW    128
#define CC    96
#define BB    16
#define RPC   32            // output rows per CTA
#define SR    38            // smem rows = RPC + 6
#define SROWH 136           // smem row stride in HALVES (272B)
#define NT    256

__device__ __forceinline__ __half2 u2h(unsigned u) { return *reinterpret_cast<__half2*>(&u); }

__global__ __launch_bounds__(NT, 6)
void morph7x7_h2_kernel(const float* __restrict__ x,
                        const float* __restrict__ wt,
                        float* __restrict__ out) {
    __shared__ __half xs[SR * SROWH];
    __shared__ uint4  wq[32];               // [s=0..7][q=0..3] quad-paired weights

    const int bid   = blockIdx.x;
    const int rtile = bid & 3;
    const int plane = bid >> 2;             // b*CC + c
    const int c     = plane % CC;
    const int R0    = rtile * RPC;

    const float* gx = x   + (size_t)plane * (HH * WW);
    float*       go = out + (size_t)plane * (HH * WW);
    const int tid = threadIdx.x;

    // ---- zero slab (borders must be literal zeros) ----
    const uint4 z4 = {0u, 0u, 0u, 0u};
    #pragma unroll
    for (int i = tid; i < (SR * SROWH) / 8; i += NT)
        reinterpret_cast<uint4*>(xs)[i] = z4;

    // ---- quad-paired weight table ----
    // wq[s*4+q] = (w2[s][2q], w2[s-1][2q], w2[s][2q+1], w2[s-1][2q+1]);
    // row s>=7 or s-1<0 or j>=7 slots are 0 (never read by the guarded loop).
    if (tid < 32) {
        const int s = tid >> 2, q = tid & 3;
        const int j0 = 2 * q, j1 = 2 * q + 1;
        unsigned e[4] = {0u, 0u, 0u, 0u};
        if (s < 7) {
            __half2 h2 = __half2half2(__float2half_rn(wt[c * 49 + s * 7 + j0]));
            e[0] = *reinterpret_cast<unsigned*>(&h2);
            if (j1 < 7) {
                __half2 g2 = __half2half2(__float2half_rn(wt[c * 49 + s * 7 + j1]));
                e[2] = *reinterpret_cast<unsigned*>(&g2);
            }
        }
        if (s > 0) {
            __half2 h2 = __half2half2(__float2half_rn(wt[c * 49 + (s - 1) * 7 + j0]));
            e[1] = *reinterpret_cast<unsigned*>(&h2);
            if (j1 < 7) {
                __half2 g2 = __half2half2(__float2half_rn(wt[c * 49 + (s - 1) * 7 + j1]));
                e[3] = *reinterpret_cast<unsigned*>(&g2);
            }
        }
        wq[tid] = make_uint4(e[0], e[1], e[2], e[3]);
    }
    __syncthreads();

    // ---- load interior rows [g0,g1), fp32 -> fp16, data at half-col 4 ----
    const int g0 = (R0 - 3 > 0) ? R0 - 3 : 0;
    const int g1 = (R0 + 35 < HH) ? R0 + 35 : HH;
    const int n4 = (g1 - g0) * 32;          // float4 count
    #pragma unroll 4
    for (int idx = tid; idx < n4; idx += NT) {
        const int rr = idx >> 5;
        const int c4 = idx & 31;
        const int g  = g0 + rr;
        float4 v = reinterpret_cast<const float4*>(gx + g * WW)[c4];
        __half2 p0 = __floats2half2_rn(v.x, v.y);
        __half2 p1 = __floats2half2_rn(v.z, v.w);
        __half2* dst = reinterpret_cast<__half2*>(&xs[(g + 3 - R0) * SROWH + 4 + c4 * 4]);
        dst[0] = p0;
        dst[1] = p1;
    }
    __syncthreads();

    // ---- compute: thread = 8 cols x 2 rows ----
    const int tx    = tid & 15;
    const int ty    = tid >> 4;
    const int cbase = tx * 8;               // output col base; LDS.128-aligned reads
    const int r0    = ty * 2;

    // S[0..3]=0 pad; taps for output col w are S[w+1 .. w+7].
    const uint4* rb = reinterpret_cast<const uint4*>(&xs[r0 * SROWH + cbase]);

    __half2 acc0[4], acc1[4];
    const __half2 h2z = __float2half2_rn(0.0f);
    #pragma unroll
    for (int p = 0; p < 4; ++p) { acc0[p] = h2z; acc1[p] = h2z; }   // folds ReLU

    #pragma unroll
    for (int s = 0; s < 8; ++s) {
        const uint4 A = rb[s * 17];
        const uint4 B = rb[s * 17 + 1];
        const unsigned h[8] = {A.x, A.y, A.z, A.w, B.x, B.y, B.z, B.w};
        unsigned sft[7];
        #pragma unroll
        for (int m = 0; m < 7; ++m) sft[m] = __byte_perm(h[m], h[m + 1], 0x5432);

        // acc0 uses weight row s (s<7); acc1 uses weight row s-1 (s>0).
        // tap j even -> sft[j/2+p]; j odd -> h[(j+1)/2+p].
        #pragma unroll
        for (int q = 0; q < 4; ++q) {
            const uint4 w = wq[s * 4 + q];       // one broadcast LDS.128: 2 taps x 2 rows
            // j = 2q (even)
            #pragma unroll
            for (int p = 0; p < 4; ++p) {
                const __half2 tap = u2h(sft[q + p]);
                if (s < 7) acc0[p] = __hmax2(acc0[p], __hadd2(tap, u2h(w.x)));
                if (s > 0) acc1[p] = __hmax2(acc1[p], __hadd2(tap, u2h(w.y)));
            }
            // j = 2q+1 (odd), skip j==7
            if (q < 3) {
                #pragma unroll
                for (int p = 0; p < 4; ++p) {
                    const __half2 tap = u2h(h[q + 1 + p]);
                    if (s < 7) acc0[p] = __hmax2(acc0[p], __hadd2(tap, u2h(w.z)));
                    if (s > 0) acc1[p] = __hmax2(acc1[p], __hadd2(tap, u2h(w.w)));
                }
            }
        }
    }

    // ---- convert fp16 -> fp32, store 2x STG.128 per row ----
    {
        float2 f0 = __half22float2(acc0[0]);
        float2 f1 = __half22float2(acc0[1]);
        float2 f2 = __half22float2(acc0[2]);
        float2 f3 = __half22float2(acc0[3]);
        float4* op = reinterpret_cast<float4*>(&go[(R0 + r0) * WW + cbase]);
        op[0] = make_float4(f0.x, f0.y, f1.x, f1.y);
        op[1] = make_float4(f2.x, f2.y, f3.x, f3.y);
    }
    {
        float2 f0 = __half22float2(acc1[0]);
        float2 f1 = __half22float2(acc1[1]);
        float2 f2 = __half22float2(acc1[2]);
        float2 f3 = __half22float2(acc1[3]);
        float4* op = reinterpret_cast<float4*>(&go[(R0 + r0 + 1) * WW + cbase]);
        op[0] = make_float4(f0.x, f0.y, f1.x, f1.y);
        op[1] = make_float4(f2.x, f2.y, f3.x, f3.y);
    }
}

extern "C" void kernel_launch(void* const* d_in, const int* in_sizes, int n_in,
                              void* d_out, int out_size) {
    const float* x  = (const float*)d_in[0];
    const float* wt = (const float*)d_in[1];
    float* out = (float*)d_out;
    morph7x7_h2_kernel<<<BB * CC * 4, NT>>>(x, wt, out);
}

// round 15
// speedup vs baseline: 1.1964x; 1.0720x over previous
#include <cuda_runtime.h>
#include <cuda_fp16.h>

// Morphological dilation2d, K=7, PAD=3 (zero padding = nn.Unfold), then ReLU.
// out[b,c,h,w] = max(0, max_{i,j}( xp[b,c,h+i,w+j] + weight[c,i,j] ))
// Packed fp16x2 (HADD2 + HMNMX2); ReLU folded into acc init (=0).
//
// R14 structure + 7 CTAs/SM (grid 6144, conc 1036 -> 5.93 waves, 93%-full tail;
// occ ~85%). Quad-paired weight table: one broadcast LDS.128 serves
// two taps x two kernel rows.
//
// x:      (16, 96, 128, 128) fp32 -> d_in[0]
// weight: (96, 7, 7)         fp32 -> d_in[1]
// out:    fp32

#define HH    128
#define WW    128
#define CC    96
#define BB    16
#define RPC   32            // output rows per CTA
#define SR    38            // smem rows = RPC + 6
#define SROWH 136           // smem row stride in HALVES (272B)
#define NT    256

__device__ __forceinline__ __half2 u2h(unsigned u) { return *reinterpret_cast<__half2*>(&u); }

__global__ __launch_bounds__(NT, 7)
void morph7x7_h2_kernel(const float* __restrict__ x,
                        const float* __restrict__ wt,
                        float* __restrict__ out) {
    __shared__ __half xs[SR * SROWH];
    __shared__ uint4  wq[32];               // [s=0..7][q=0..3] quad-paired weights

    const int bid   = blockIdx.x;
    const int rtile = bid & 3;
    const int plane = bid >> 2;             // b*CC + c
    const int c     = plane % CC;
    const int R0    = rtile * RPC;

    const float* gx = x + (size_t)plane * (HH * WW);
    const int tid = threadIdx.x;

    // ---- zero slab (borders must be literal zeros) ----
    const uint4 z4 = {0u, 0u, 0u, 0u};
    #pragma unroll
    for (int i = tid; i < (SR * SROWH) / 8; i += NT)
        reinterpret_cast<uint4*>(xs)[i] = z4;

    // ---- quad-paired weight table ----
    // wq[s*4+q] = (w2[s][2q], w2[s-1][2q], w2[s][2q+1], w2[s-1][2q+1]);
    // out-of-range slots are 0 (never read by the guarded loop).
    if (tid < 32) {
        const int s = tid >> 2, q = tid & 3;
        const int j0 = 2 * q, j1 = 2 * q + 1;
        unsigned e[4] = {0u, 0u, 0u, 0u};
        if (s < 7) {
            __half2 h2 = __half2half2(__float2half_rn(wt[c * 49 + s * 7 + j0]));
            e[0] = *reinterpret_cast<unsigned*>(&h2);
            if (j1 < 7) {
                __half2 g2 = __half2half2(__float2half_rn(wt[c * 49 + s * 7 + j1]));
                e[2] = *reinterpret_cast<unsigned*>(&g2);
            }
        }
        if (s > 0) {
            __half2 h2 = __half2half2(__float2half_rn(wt[c * 49 + (s - 1) * 7 + j0]));
            e[1] = *reinterpret_cast<unsigned*>(&h2);
            if (j1 < 7) {
                __half2 g2 = __half2half2(__float2half_rn(wt[c * 49 + (s - 1) * 7 + j1]));
                e[3] = *reinterpret_cast<unsigned*>(&g2);
            }
        }
        wq[tid] = make_uint4(e[0], e[1], e[2], e[3]);
    }
    __syncthreads();

    // ---- load interior rows [g0,g1), fp32 -> fp16, data at half-col 4 ----
    const int g0 = (R0 - 3 > 0) ? R0 - 3 : 0;
    const int g1 = (R0 + 35 < HH) ? R0 + 35 : HH;
    const int n4 = (g1 - g0) * 32;          // float4 count
    for (int idx = tid; idx < n4; idx += NT) {
        const int rr = idx >> 5;
        const int c4 = idx & 31;
        const int g  = g0 + rr;
        float4 v = reinterpret_cast<const float4*>(gx + g * WW)[c4];
        __half2 p0 = __floats2half2_rn(v.x, v.y);
        __half2 p1 = __floats2half2_rn(v.z, v.w);
        __half2* dst = reinterpret_cast<__half2*>(&xs[(g + 3 - R0) * SROWH + 4 + c4 * 4]);
        dst[0] = p0;
        dst[1] = p1;
    }
    __syncthreads();

    // ---- compute: thread = 8 cols x 2 rows ----
    const int tx    = tid & 15;
    const int ty    = tid >> 4;
    const int cbase = tx * 8;               // output col base; LDS.128-aligned reads
    const int r0    = ty * 2;

    // S[0..3]=0 pad; taps for output col w are S[w+1 .. w+7].
    const uint4* rb = reinterpret_cast<const uint4*>(&xs[r0 * SROWH + cbase]);

    __half2 acc0[4], acc1[4];
    const __half2 h2z = __float2half2_rn(0.0f);
    #pragma unroll
    for (int p = 0; p < 4; ++p) { acc0[p] = h2z; acc1[p] = h2z; }   // folds ReLU

    #pragma unroll
    for (int s = 0; s < 8; ++s) {
        const uint4 A = rb[s * 17];
        const uint4 B = rb[s * 17 + 1];
        const unsigned h[8] = {A.x, A.y, A.z, A.w, B.x, B.y, B.z, B.w};
        unsigned sft[7];
        #pragma unroll
        for (int m = 0; m < 7; ++m) sft[m] = __byte_perm(h[m], h[m + 1], 0x5432);

        // acc0 uses weight row s (s<7); acc1 uses weight row s-1 (s>0).
        // tap j even -> sft[j/2+p]; j odd -> h[(j+1)/2+p].
        #pragma unroll
        for (int q = 0; q < 4; ++q) {
            const uint4 w = wq[s * 4 + q];       // one broadcast LDS.128: 2 taps x 2 rows
            // j = 2q (even)
            #pragma unroll
            for (int p = 0; p < 4; ++p) {
                const __half2 tap = u2h(sft[q + p]);
                if (s < 7) acc0[p] = __hmax2(acc0[p], __hadd2(tap, u2h(w.x)));
                if (s > 0) acc1[p] = __hmax2(acc1[p], __hadd2(tap, u2h(w.y)));
            }
            // j = 2q+1 (odd), skip j==7
            if (q < 3) {
                #pragma unroll
                for (int p = 0; p < 4; ++p) {
                    const __half2 tap = u2h(h[q + 1 + p]);
                    if (s < 7) acc0[p] = __hmax2(acc0[p], __hadd2(tap, u2h(w.z)));
                    if (s > 0) acc1[p] = __hmax2(acc1[p], __hadd2(tap, u2h(w.w)));
                }
            }
        }
    }

    // ---- convert fp16 -> fp32, store 2x STG.128 per row ----
    float* go = out + (size_t)plane * (HH * WW);
    {
        float2 f0 = __half22float2(acc0[0]);
        float2 f1 = __half22float2(acc0[1]);
        float2 f2 = __half22float2(acc0[2]);
        float2 f3 = __half22float2(acc0[3]);
        float4* op = reinterpret_cast<float4*>(&go[(R0 + r0) * WW + cbase]);
        op[0] = make_float4(f0.x, f0.y, f1.x, f1.y);
        op[1] = make_float4(f2.x, f2.y, f3.x, f3.y);
    }
    {
        float2 f0 = __half22float2(acc1[0]);
        float2 f1 = __half22float2(acc1[1]);
        float2 f2 = __half22float2(acc1[2]);
        float2 f3 = __half22float2(acc1[3]);
        float4* op = reinterpret_cast<float4*>(&go[(R0 + r0 + 1) * WW + cbase]);
        op[0] = make_float4(f0.x, f0.y, f1.x, f1.y);
        op[1] = make_float4(f2.x, f2.y, f3.x, f3.y);
    }
}

extern "C" void kernel_launch(void* const* d_in, const int* in_sizes, int n_in,
                              void* d_out, int out_size) {
    const float* x  = (const float*)d_in[0];
    const float* wt = (const float*)d_in[1];
    float* out = (float*)d_out;
    morph7x7_h2_kernel<<<BB * CC * 4, NT>>>(x, wt, out);
}